// round 11
// baseline (speedup 1.0000x reference)
#include <cuda_runtime.h>

#define N_CELL  50000
#define N_NET   10000
#define N_GCELL 20000
#define NE      100000
#define D       32
#define DPF     16
#define GP      17            // DPF + 1 (bias row)
#define TSRC    16
#define NWRP    17            // warps per 544-thread block
#define NB_NET  (N_NET / TSRC)      // 625
#define NB_GC   (N_GCELL / TSRC)    // 1250
#define CAP_PINS 512          // pins dst-bin capacity (mean 160)
#define CAP_CONN 256          // connect dst-bin capacity (mean 80)
#define CAP_PT   256          // pt dst-bin capacity (mean 80)
#define CAPN    512           // pinned src-bin capacity (mean 160)
#define CAPH    256           // pf src-bin capacity (mean 80)

// ---------------- scratch (static device globals; no allocs) ------------
__device__ __align__(16) float g_agg_cell_pd[N_CELL * D];
__device__ __align__(16) float g_agg_cell_pf[N_CELL * D];
__device__ __align__(16) int g_cnt_pins_src[N_CELL];
__device__ __align__(16) int g_cnt_connect_src[N_GCELL];
__device__ __align__(16) int g_cnt_pt_src[N_CELL];
__device__ __align__(16) int g_cnt_pinned_dst[N_CELL];
__device__ __align__(16) int g_cnt_pf_dst[N_CELL];
__device__ __align__(16) int g_bc_pins[NB_NET];
__device__ __align__(16) int g_bc_conn[NB_GC];
__device__ __align__(16) int g_bc_pt[NB_GC];
__device__ __align__(16) int g_bc_pinned[NB_NET];
__device__ __align__(16) int g_bc_pf[NB_GC];
__device__ int g_bin_pins[NB_NET * CAP_PINS];   // packed (src<<4)|(dst&15)
__device__ int g_bin_conn[NB_GC * CAP_CONN];    // packed
__device__ int g_bin_pt[NB_GC * CAP_PT];        // packed
__device__ int g_bin_pinned[NB_NET * CAPN];     // eid
__device__ int g_bin_pf[NB_GC * CAPH];          // eid

// vector reduction to global (sm_90+)
__device__ __forceinline__ void red_add_f4(float* p, float4 v) {
    asm volatile("red.global.add.v4.f32 [%0], {%1,%2,%3,%4};"
                 :: "l"(p), "f"(v.x), "f"(v.y), "f"(v.z), "f"(v.w) : "memory");
}

// ---------------- kernels ----------------

__global__ void k_zero() {
    int tid = blockIdx.x * blockDim.x + threadIdx.x;
    int stride = gridDim.x * blockDim.x;
    float4 z4 = {0.f, 0.f, 0.f, 0.f};
    int4 zi = {0, 0, 0, 0};
    for (int i = tid; i < N_CELL * D / 4; i += stride) { ((float4*)g_agg_cell_pd)[i] = z4; ((float4*)g_agg_cell_pf)[i] = z4; }
    for (int i = tid; i < N_CELL / 4; i += stride) {
        ((int4*)g_cnt_pins_src)[i] = zi; ((int4*)g_cnt_pt_src)[i] = zi;
        ((int4*)g_cnt_pinned_dst)[i] = zi; ((int4*)g_cnt_pf_dst)[i] = zi;
    }
    for (int i = tid; i < N_GCELL / 4; i += stride) ((int4*)g_cnt_connect_src)[i] = zi;
    for (int i = tid; i < NB_NET; i += stride) { g_bc_pins[i] = 0; g_bc_pinned[i] = 0; }
    for (int i = tid; i < NB_GC; i += stride) { g_bc_conn[i] = 0; g_bc_pt[i] = 0; g_bc_pf[i] = 0; }
}

#define RBLK ((NE + 255) / 256)      // 391 blocks per role

// prep for the gather branch: src counts + dst-keyed packed bins
__global__ void k_prep_gc(const int* __restrict__ pins_src, const int* __restrict__ pins_dst,
                          const int* __restrict__ connect_src, const int* __restrict__ connect_dst,
                          const int* __restrict__ pt_src, const int* __restrict__ pt_dst) {
    int role = blockIdx.x / RBLK;
    int e = (blockIdx.x - role * RBLK) * 256 + threadIdx.x;
    if (e >= NE) return;
    switch (role) {
        case 0: atomicAdd(&g_cnt_pins_src[pins_src[e]], 1); break;
        case 1: atomicAdd(&g_cnt_connect_src[connect_src[e]], 1); break;
        case 2: atomicAdd(&g_cnt_pt_src[pt_src[e]], 1); break;
        case 3: {
            int d = pins_dst[e], b = d >> 4;
            int s = atomicAdd(&g_bc_pins[b], 1);
            if (s < CAP_PINS) g_bin_pins[b * CAP_PINS + s] = (pins_src[e] << 4) | (d & 15);
            break;
        }
        case 4: {
            int d = connect_dst[e], b = d >> 4;
            int s = atomicAdd(&g_bc_conn[b], 1);
            if (s < CAP_CONN) g_bin_conn[b * CAP_CONN + s] = (connect_src[e] << 4) | (d & 15);
            break;
        }
        default: {
            int d = pt_dst[e], b = d >> 4;
            int s = atomicAdd(&g_bc_pt[b], 1);
            if (s < CAP_PT) g_bin_pt[b * CAP_PT + s] = (pt_src[e] << 4) | (d & 15);
            break;
        }
    }
}

// prep for the nnconv branch: src-keyed eid bins + dst counts for the mean
__global__ void k_prep_nn(const int* __restrict__ pinned_src, const int* __restrict__ pinned_dst,
                          const int* __restrict__ pf_src, const int* __restrict__ pf_dst) {
    int role = blockIdx.x / RBLK;
    int e = (blockIdx.x - role * RBLK) * 256 + threadIdx.x;
    if (e >= NE) return;
    switch (role) {
        case 0: atomicAdd(&g_cnt_pinned_dst[pinned_dst[e]], 1); break;
        case 1: atomicAdd(&g_cnt_pf_dst[pf_dst[e]], 1); break;
        case 2: {
            int b = pinned_src[e] >> 4;
            int s = atomicAdd(&g_bc_pinned[b], 1);
            if (s < CAPN) g_bin_pinned[b * CAPN + s] = e;
            break;
        }
        default: {
            int b = pf_src[e] >> 4;
            int s = atomicAdd(&g_bc_pf[b], 1);
            if (s < CAPH) g_bin_pf[b * CAPH + s] = e;
            break;
        }
    }
}

// ---- gather GraphConv: no global atomics. Block owns 16 dst nodes. ----
// Warp-private smem slices: warp processes one edge at a time (32 lanes = feats),
// so slice writes are race-free and conflict-free.
__global__ __launch_bounds__(544, 2) void k_gather(
        const float* __restrict__ node_feat, const float* __restrict__ hanna_feat,
        const float* __restrict__ net_feat,
        const float* __restrict__ W_pins, const float* __restrict__ b_pins,
        const float* __restrict__ W_net, const float* __restrict__ b_net,
        const float* __restrict__ W_connect, const float* __restrict__ b_connect,
        const float* __restrict__ W_pt, const float* __restrict__ b_pt,
        float* __restrict__ out_net, float* __restrict__ out_gcell) {
    __shared__ float sl[NWRP][TSRC][D];    // 34.8 KB accumulation slices
    __shared__ int scnt[NWRP][TSRC];
    __shared__ float sagg[TSRC][D];
    __shared__ float sh_h[TSRC][D];

    int bid = blockIdx.x;
    int tid = threadIdx.x;
    int w = tid >> 5, lane = tid & 31;
    int t512 = tid >> 5;  (void)t512;

    if (bid < NB_NET) {
        // ---- net outputs: pins graphconv + dense term ----
        int first = bid * TSRC;
        for (int i = tid; i < NWRP * TSRC * D; i += 544) ((float*)sl)[i] = 0.f;
        for (int i = tid; i < NWRP * TSRC; i += 544) ((int*)scnt)[i] = 0;
        if (tid < TSRC * D) ((float*)sh_h)[tid] = net_feat[(size_t)first * D + tid];
        __syncthreads();

        int nE = min(g_bc_pins[bid], CAP_PINS);
        for (int k = w; k < nE; k += NWRP) {
            int pk = g_bin_pins[bid * CAP_PINS + k];
            int s = pk >> 4, t = pk & 15;
            float v = node_feat[(size_t)s * D + lane] * rsqrtf((float)max(g_cnt_pins_src[s], 1));
            sl[w][t][lane] += v;
            if (lane == 0) scnt[w][t]++;
        }
        __syncthreads();
        if (tid < TSRC * D) {
            int t = tid >> 5, o = tid & 31;
            float r = 0.f;
#pragma unroll
            for (int ww = 0; ww < NWRP; ww++) r += sl[ww][t][o];
            sagg[t][o] = r;
        } else if (tid < TSRC * D + TSRC) {
            int t = tid - TSRC * D;
            int c = 0;
#pragma unroll
            for (int ww = 0; ww < NWRP; ww++) c += scnt[ww][t];
            scnt[0][t] = c;
        }
        __syncthreads();
        if (tid < TSRC * D) {
            int t = tid >> 5, o = tid & 31;
            float acc = 0.f, acc2 = 0.f;
#pragma unroll
            for (int i = 0; i < D; i++) {
                acc  = fmaf(sagg[t][i], W_pins[i * D + o], acc);
                acc2 = fmaf(sh_h[t][i], W_net[i * D + o], acc2);
            }
            float dn = rsqrtf((float)max(scnt[0][t], 1));
            out_net[(size_t)(first + t) * D + o] = acc * dn + b_pins[o] + acc2 + b_net[o];
        }
    } else {
        // ---- gcell outputs: connect (hanna) + pt (node) graphconvs ----
        int gb = bid - NB_NET;
        int first = gb * TSRC;
        float accA = 0.f;
        int t = tid >> 5, o = tid & 31;

        // phase A: connect
        for (int i = tid; i < NWRP * TSRC * D; i += 544) ((float*)sl)[i] = 0.f;
        for (int i = tid; i < NWRP * TSRC; i += 544) ((int*)scnt)[i] = 0;
        __syncthreads();
        int nA = min(g_bc_conn[gb], CAP_CONN);
        for (int k = w; k < nA; k += NWRP) {
            int pk = g_bin_conn[gb * CAP_CONN + k];
            int s = pk >> 4, tt = pk & 15;
            float v = hanna_feat[(size_t)s * D + lane] * rsqrtf((float)max(g_cnt_connect_src[s], 1));
            sl[w][tt][lane] += v;
            if (lane == 0) scnt[w][tt]++;
        }
        __syncthreads();
        if (tid < TSRC * D) {
            float r = 0.f;
#pragma unroll
            for (int ww = 0; ww < NWRP; ww++) r += sl[ww][t][o];
            sagg[t][o] = r;
        } else if (tid < TSRC * D + TSRC) {
            int tt = tid - TSRC * D;
            int c = 0;
#pragma unroll
            for (int ww = 0; ww < NWRP; ww++) c += scnt[ww][tt];
            scnt[0][tt] = c;
        }
        __syncthreads();
        if (tid < TSRC * D) {
            float acc = 0.f;
#pragma unroll
            for (int i = 0; i < D; i++) acc = fmaf(sagg[t][i], W_connect[i * D + o], acc);
            accA = acc * rsqrtf((float)max(scnt[0][t], 1));
        }
        __syncthreads();

        // phase B: pt
        for (int i = tid; i < NWRP * TSRC * D; i += 544) ((float*)sl)[i] = 0.f;
        for (int i = tid; i < NWRP * TSRC; i += 544) ((int*)scnt)[i] = 0;
        __syncthreads();
        int nB = min(g_bc_pt[gb], CAP_PT);
        for (int k = w; k < nB; k += NWRP) {
            int pk = g_bin_pt[gb * CAP_PT + k];
            int s = pk >> 4, tt = pk & 15;
            float v = node_feat[(size_t)s * D + lane] * rsqrtf((float)max(g_cnt_pt_src[s], 1));
            sl[w][tt][lane] += v;
            if (lane == 0) scnt[w][tt]++;
        }
        __syncthreads();
        if (tid < TSRC * D) {
            float r = 0.f;
#pragma unroll
            for (int ww = 0; ww < NWRP; ww++) r += sl[ww][t][o];
            sagg[t][o] = r;
        } else if (tid < TSRC * D + TSRC) {
            int tt = tid - TSRC * D;
            int c = 0;
#pragma unroll
            for (int ww = 0; ww < NWRP; ww++) c += scnt[ww][tt];
            scnt[0][tt] = c;
        }
        __syncthreads();
        if (tid < TSRC * D) {
            float acc = 0.f;
#pragma unroll
            for (int i = 0; i < D; i++) acc = fmaf(sagg[t][i], W_pt[i * D + o], acc);
            float accB = acc * rsqrtf((float)max(scnt[0][t], 1));
            out_gcell[(size_t)(first + t) * D + o] = accA + b_connect[o] + accB + b_pt[o];
        }
    }
}

// Fused NNConv: block owns TSRC=16 consecutive source nodes (== one bin).
__global__ __launch_bounds__(544, 2) void k_nn(
        const float* __restrict__ net_feat, const float* __restrict__ hanna_feat,
        const float* __restrict__ W_topo, const float* __restrict__ b_topo,
        const float* __restrict__ pin_feat, const float* __restrict__ edge_feat,
        const int* __restrict__ pinned_src, const int* __restrict__ pinned_dst,
        const int* __restrict__ pf_src, const int* __restrict__ pf_dst) {
    __shared__ float4 sh_h4[TSRC * 8];            // 16 rows x 32 feats
    __shared__ float sh_G[TSRC * GP * D];         // 16 x 17 x 32 = 34.8 KB

    int bid = blockIdx.x;
    const float* h; const float* ef; const int* srcA; const int* dstA;
    const int* bins; const int* bincnt; float* agg; int first, cap, bin;
    if (bid < NB_NET) {
        bin = bid; first = bid * TSRC;
        h = net_feat; ef = pin_feat; srcA = pinned_src; dstA = pinned_dst;
        bins = g_bin_pinned; bincnt = g_bc_pinned; agg = g_agg_cell_pd; cap = CAPN;
    } else {
        bin = bid - NB_NET; first = bin * TSRC;
        h = hanna_feat; ef = edge_feat; srcA = pf_src; dstA = pf_dst;
        bins = g_bin_pf; bincnt = g_bc_pf; agg = g_agg_cell_pf; cap = CAPH;
    }
    int tid = threadIdx.x;

    if (tid < TSRC * D) ((float*)sh_h4)[tid] = h[(size_t)first * D + tid];
    __syncthreads();

    // ---- phase 1: G compute (thread = (p, o), 16 accumulators) ----
    {
        int p = tid >> 5, o = tid & 31;
        const float* w = ((p < DPF) ? (W_topo + p * (D * D)) : b_topo) + o;
        float acc[TSRC];
#pragma unroll
        for (int t = 0; t < TSRC; t++) acc[t] = 0.f;
#pragma unroll
        for (int i4 = 0; i4 < 8; i4++) {
            float w0 = w[(i4 * 4 + 0) * D];
            float w1 = w[(i4 * 4 + 1) * D];
            float w2 = w[(i4 * 4 + 2) * D];
            float w3 = w[(i4 * 4 + 3) * D];
#pragma unroll
            for (int t = 0; t < TSRC; t++) {
                float4 h4 = sh_h4[t * 8 + i4];
                acc[t] = fmaf(h4.x, w0, fmaf(h4.y, w1, fmaf(h4.z, w2, fmaf(h4.w, w3, acc[t]))));
            }
        }
#pragma unroll
        for (int t = 0; t < TSRC; t++) sh_G[t * (GP * D) + p * D + o] = acc[t];
    }
    __syncthreads();

    // ---- phase 2: edge streaming from this block's bin ----
    int bs = bin * cap;
    int nE = min(bincnt[bin], cap);
    int grp = tid >> 3;        // 68 groups of 8
    int j8 = tid & 7;
    int iters = (nE + 67) / 68;
    for (int it = 0; it < iters; it++) {
        int j = it * 68 + grp;
        bool valid = j < nE;
        int eid = bins[bs + (valid ? j : 0)];
        int s = srcA[eid];
        int t = s - first;
        int d = dstA[eid];
        float2 c2 = ((const float2*)(ef + (size_t)eid * DPF))[j8];
        const float* Gt = sh_G + t * (GP * D);
        float4 a = {0.f, 0.f, 0.f, 0.f};
#pragma unroll
        for (int p = 0; p < GP; p++) {
            float cp;
            if (p < DPF) cp = __shfl_sync(0xffffffffu, (p & 1) ? c2.y : c2.x, p >> 1, 8);
            else cp = 1.f;
            float4 g4 = ((const float4*)(Gt + p * D))[j8];
            a.x = fmaf(cp, g4.x, a.x);
            a.y = fmaf(cp, g4.y, a.y);
            a.z = fmaf(cp, g4.z, a.z);
            a.w = fmaf(cp, g4.w, a.w);
        }
        if (valid) red_add_f4(agg + (size_t)d * D + j8 * 4, a);
    }
}

// cell epilogue only (net/gcell written by k_gather)
__global__ void k_final_cell(const float* __restrict__ b_pinned, const float* __restrict__ b_pf,
                             float* __restrict__ out_cell) {
    int idx = blockIdx.x * blockDim.x + threadIdx.x;
    if (idx >= N_CELL * D) return;
    int c = idx >> 5, o = idx & 31;
    float d1 = (float)max(g_cnt_pinned_dst[c], 1);
    float d2 = (float)max(g_cnt_pf_dst[c], 1);
    out_cell[idx] = g_agg_cell_pd[idx] / d1 + b_pinned[o]
                  + g_agg_cell_pf[idx] / d2 + b_pf[o];
}

// ---------------- launch ----------------

extern "C" void kernel_launch(void* const* d_in, const int* in_sizes, int n_in,
                              void* d_out, int out_size) {
    const float* node_feat   = (const float*)d_in[0];
    const float* net_feat    = (const float*)d_in[1];
    const float* pin_feat    = (const float*)d_in[2];
    const float* hanna_feat  = (const float*)d_in[3];
    const float* edge_feat   = (const float*)d_in[4];
    const int* pins_src      = (const int*)d_in[5];
    const int* pins_dst      = (const int*)d_in[6];
    const int* pinned_src    = (const int*)d_in[7];
    const int* pinned_dst    = (const int*)d_in[8];
    const int* connect_src   = (const int*)d_in[9];
    const int* connect_dst   = (const int*)d_in[10];
    const int* pt_src        = (const int*)d_in[11];
    const int* pt_dst        = (const int*)d_in[12];
    const int* pf_src        = (const int*)d_in[13];
    const int* pf_dst        = (const int*)d_in[14];
    const float* W_net       = (const float*)d_in[15];
    const float* b_net       = (const float*)d_in[16];
    const float* W_topo      = (const float*)d_in[17];
    const float* b_topo      = (const float*)d_in[18];
    const float* W_pins      = (const float*)d_in[19];
    const float* b_pins      = (const float*)d_in[20];
    const float* W_connect   = (const float*)d_in[21];
    const float* b_connect   = (const float*)d_in[22];
    const float* W_pt        = (const float*)d_in[23];
    const float* b_pt        = (const float*)d_in[24];
    const float* b_pinned    = (const float*)d_in[25];
    const float* b_pf        = (const float*)d_in[26];

    float* out       = (float*)d_out;
    float* out_cell  = out;
    float* out_net   = out + (size_t)N_CELL * D;
    float* out_gcell = out + (size_t)(N_CELL + N_NET) * D;

    static cudaStream_t s1 = nullptr;
    static cudaEvent_t evZ = nullptr, evEnd = nullptr;
    if (s1 == nullptr) {
        cudaStreamCreateWithFlags(&s1, cudaStreamNonBlocking);
        cudaEventCreateWithFlags(&evZ, cudaEventDisableTiming);
        cudaEventCreateWithFlags(&evEnd, cudaEventDisableTiming);
    }

    // main: zero
    k_zero<<<592, 256>>>();
    cudaEventRecord(evZ, 0);

    // s1 branch: nnconv chain (prep_nn -> nn -> final_cell)
    cudaStreamWaitEvent(s1, evZ, 0);
    k_prep_nn<<<4 * RBLK, 256, 0, s1>>>(pinned_src, pinned_dst, pf_src, pf_dst);
    k_nn<<<NB_NET + NB_GC, 544, 0, s1>>>(net_feat, hanna_feat, W_topo, b_topo,
                                         pin_feat, edge_feat,
                                         pinned_src, pinned_dst, pf_src, pf_dst);
    k_final_cell<<<(N_CELL * D + 255) / 256, 256, 0, s1>>>(b_pinned, b_pf, out_cell);
    cudaEventRecord(evEnd, s1);

    // main branch: gather chain (prep_gc -> gather), writes out_net/out_gcell
    k_prep_gc<<<6 * RBLK, 256>>>(pins_src, pins_dst, connect_src, connect_dst,
                                 pt_src, pt_dst);
    k_gather<<<NB_NET + NB_GC, 544>>>(node_feat, hanna_feat, net_feat,
                                      W_pins, b_pins, W_net, b_net,
                                      W_connect, b_connect, W_pt, b_pt,
                                      out_net, out_gcell);

    // join
    cudaStreamWaitEvent(0, evEnd, 0);
}

// round 12
// speedup vs baseline: 1.8436x; 1.8436x over previous
#include <cuda_runtime.h>

#define N_CELL  50000
#define N_NET   10000
#define N_GCELL 20000
#define NE      100000
#define D       32
#define DPF     16
#define GP      17           // DPF + 1 (bias row)
#define TSRC    16           // source nodes per fused-nnconv block
#define NB_NET_NN (N_NET / TSRC)     // 625
#define NB_GC_NN  (N_GCELL / TSRC)   // 1250
#define CAPN    512          // bin capacity, net side (mean 160)
#define CAPH    256          // bin capacity, gcell side (mean 80)

// ---------------- scratch (static device globals; no allocs) ------------
__device__ __align__(16) float g_agg_net[N_NET * D];
__device__ __align__(16) float g_agg_gc_c[N_GCELL * D];
__device__ __align__(16) float g_agg_gc_pt[N_GCELL * D];
__device__ __align__(16) int g_cnt_pins_src[N_CELL];
__device__ __align__(16) int g_cnt_pins_dst[N_NET];
__device__ __align__(16) int g_cnt_pinned_dst[N_CELL];
__device__ __align__(16) int g_cnt_connect_src[N_GCELL];
__device__ __align__(16) int g_cnt_connect_dst[N_GCELL];
__device__ __align__(16) int g_cnt_pt_src[N_CELL];
__device__ __align__(16) int g_cnt_pt_dst[N_GCELL];
__device__ __align__(16) int g_cnt_pf_dst[N_CELL];
__device__ __align__(16) int g_bincnt_net[NB_NET_NN];
__device__ __align__(16) int g_bincnt_han[NB_GC_NN];
__device__ int g_bin_net[NB_NET_NN * CAPN];
__device__ int g_bin_han[NB_GC_NN * CAPH];

// vector reduction to global (sm_90+)
__device__ __forceinline__ void red_add_f4(float* p, float4 v) {
    asm volatile("red.global.add.v4.f32 [%0], {%1,%2,%3,%4};"
                 :: "l"(p), "f"(v.x), "f"(v.y), "f"(v.z), "f"(v.w) : "memory");
}

// ---------------- kernels ----------------

// zero counts/bins/aggs; pre-init out_cell with summed biases (k_nn REDs into it)
__global__ void k_zero(const float* __restrict__ b_pinned, const float* __restrict__ b_pf,
                       float* __restrict__ out_cell) {
    __shared__ float4 sb4[8];
    if (threadIdx.x < D) {
        float v = b_pinned[threadIdx.x] + b_pf[threadIdx.x];
        ((float*)sb4)[threadIdx.x] = v;
    }
    __syncthreads();
    int tid = blockIdx.x * blockDim.x + threadIdx.x;
    int stride = gridDim.x * blockDim.x;
    float4 z4 = {0.f, 0.f, 0.f, 0.f};
    int4 zi = {0, 0, 0, 0};
    for (int i = tid; i < N_CELL * D / 4; i += stride) {
        ((float4*)out_cell)[i] = sb4[i & 7];
    }
    for (int i = tid; i < N_NET * D / 4; i += stride) ((float4*)g_agg_net)[i] = z4;
    for (int i = tid; i < N_GCELL * D / 4; i += stride) { ((float4*)g_agg_gc_c)[i] = z4; ((float4*)g_agg_gc_pt)[i] = z4; }
    for (int i = tid; i < N_CELL / 4; i += stride) {
        ((int4*)g_cnt_pins_src)[i] = zi; ((int4*)g_cnt_pinned_dst)[i] = zi;
        ((int4*)g_cnt_pt_src)[i] = zi;   ((int4*)g_cnt_pf_dst)[i] = zi;
    }
    for (int i = tid; i < N_NET / 4; i += stride) ((int4*)g_cnt_pins_dst)[i] = zi;
    for (int i = tid; i < N_GCELL / 4; i += stride) {
        ((int4*)g_cnt_connect_src)[i] = zi; ((int4*)g_cnt_connect_dst)[i] = zi;
        ((int4*)g_cnt_pt_dst)[i] = zi;
    }
    for (int i = tid; i < NB_NET_NN; i += stride) g_bincnt_net[i] = 0;
    for (int i = tid; i < NB_GC_NN; i += stride) g_bincnt_han[i] = 0;
}

#define RBLK ((NE + 255) / 256)      // 391 blocks per role

// nn-branch prefix only: dst counts (for mean scaling) + src bins
__global__ void k_prep_nn(const int* __restrict__ pinned_src, const int* __restrict__ pinned_dst,
                          const int* __restrict__ pf_src, const int* __restrict__ pf_dst) {
    int role = blockIdx.x / RBLK;
    int e = (blockIdx.x - role * RBLK) * 256 + threadIdx.x;
    if (e >= NE) return;
    switch (role) {
        case 0: atomicAdd(&g_cnt_pinned_dst[pinned_dst[e]], 1); break;
        case 1: atomicAdd(&g_cnt_pf_dst[pf_dst[e]], 1); break;
        case 2: {
            int b = pinned_src[e] >> 4;
            int s = atomicAdd(&g_bincnt_net[b], 1);
            if (s < CAPN) g_bin_net[b * CAPN + s] = e;
            break;
        }
        default: {
            int b = pf_src[e] >> 4;
            int s = atomicAdd(&g_bincnt_han[b], 1);
            if (s < CAPH) g_bin_han[b * CAPH + s] = e;
            break;
        }
    }
}

// gc-branch prefix only: src counts (for norm) + dst counts (for epilogue)
__global__ void k_prep_gc(const int* __restrict__ pins_src, const int* __restrict__ pins_dst,
                          const int* __restrict__ connect_src, const int* __restrict__ connect_dst,
                          const int* __restrict__ pt_src, const int* __restrict__ pt_dst) {
    int role = blockIdx.x / RBLK;
    int e = (blockIdx.x - role * RBLK) * 256 + threadIdx.x;
    if (e >= NE) return;
    switch (role) {
        case 0: atomicAdd(&g_cnt_pins_src[pins_src[e]], 1); break;
        case 1: atomicAdd(&g_cnt_connect_src[connect_src[e]], 1); break;
        case 2: atomicAdd(&g_cnt_pt_src[pt_src[e]], 1); break;
        case 3: atomicAdd(&g_cnt_pins_dst[pins_dst[e]], 1); break;
        case 4: atomicAdd(&g_cnt_connect_dst[connect_dst[e]], 1); break;
        default: atomicAdd(&g_cnt_pt_dst[pt_dst[e]], 1); break;
    }
}

// GraphConv scatter: 8 threads/edge, float4 vector REDs. 3 edge sets. (unchanged from 121.6µs best)
__global__ void k_gc_scatter(const float* __restrict__ node_feat, const float* __restrict__ hanna_feat,
                             const int* __restrict__ pins_src, const int* __restrict__ pins_dst,
                             const int* __restrict__ connect_src, const int* __restrict__ connect_dst,
                             const int* __restrict__ pt_src, const int* __restrict__ pt_dst) {
    int gt = blockIdx.x * blockDim.x + threadIdx.x;
    int ge = gt >> 3;
    int j = gt & 7;
    if (ge >= 3 * NE) return;
    const float* feat; const int* srcA; const int* dstA; const int* cnt; float* agg; int e;
    if (ge < NE)          { e = ge;          feat = node_feat;  srcA = pins_src;    dstA = pins_dst;    cnt = g_cnt_pins_src;    agg = g_agg_net;   }
    else if (ge < 2 * NE) { e = ge - NE;     feat = hanna_feat; srcA = connect_src; dstA = connect_dst; cnt = g_cnt_connect_src; agg = g_agg_gc_c;  }
    else                  { e = ge - 2 * NE; feat = node_feat;  srcA = pt_src;      dstA = pt_dst;      cnt = g_cnt_pt_src;      agg = g_agg_gc_pt; }
    int s = srcA[e], d = dstA[e];
    float scale = rsqrtf((float)max(cnt[s], 1));
    float4 f = ((const float4*)(feat + (size_t)s * D))[j];
    f.x *= scale; f.y *= scale; f.z *= scale; f.w *= scale;
    red_add_f4(agg + (size_t)d * D + j * 4, f);
}

// Fused NNConv: block owns TSRC=16 consecutive source nodes (== one bin).
// Phase 1 (FFMA): G in shared. Phase 2: per-edge message scaled by 1/deg(dst),
// RED directly into bias-pre-initialized out_cell (no agg round trip, no final_cell).
__global__ __launch_bounds__(544, 2) void k_nn(
        const float* __restrict__ net_feat, const float* __restrict__ hanna_feat,
        const float* __restrict__ W_topo, const float* __restrict__ b_topo,
        const float* __restrict__ pin_feat, const float* __restrict__ edge_feat,
        const int* __restrict__ pinned_src, const int* __restrict__ pinned_dst,
        const int* __restrict__ pf_src, const int* __restrict__ pf_dst,
        float* __restrict__ out_cell) {
    __shared__ float4 sh_h4[TSRC * 8];            // 16 rows x 32 feats
    __shared__ float sh_G[TSRC * GP * D];         // 16 x 17 x 32 = 34.8 KB

    int bid = blockIdx.x;
    const float* h; const float* ef; const int* srcA; const int* dstA;
    const int* bins; const int* bincnt; const int* cntD; int first, cap, bin;
    if (bid < NB_NET_NN) {
        bin = bid; first = bid * TSRC;
        h = net_feat; ef = pin_feat; srcA = pinned_src; dstA = pinned_dst;
        bins = g_bin_net; bincnt = g_bincnt_net; cntD = g_cnt_pinned_dst; cap = CAPN;
    } else {
        bin = bid - NB_NET_NN; first = bin * TSRC;
        h = hanna_feat; ef = edge_feat; srcA = pf_src; dstA = pf_dst;
        bins = g_bin_han; bincnt = g_bincnt_han; cntD = g_cnt_pf_dst; cap = CAPH;
    }
    int tid = threadIdx.x;

    if (tid < TSRC * D) ((float*)sh_h4)[tid] = h[(size_t)first * D + tid];
    __syncthreads();

    // ---- phase 1: G compute (thread = (p, o), 16 accumulators) ----
    {
        int p = tid >> 5, o = tid & 31;
        const float* w = ((p < DPF) ? (W_topo + p * (D * D)) : b_topo) + o;
        float acc[TSRC];
#pragma unroll
        for (int t = 0; t < TSRC; t++) acc[t] = 0.f;
#pragma unroll
        for (int i4 = 0; i4 < 8; i4++) {
            float w0 = w[(i4 * 4 + 0) * D];
            float w1 = w[(i4 * 4 + 1) * D];
            float w2 = w[(i4 * 4 + 2) * D];
            float w3 = w[(i4 * 4 + 3) * D];
#pragma unroll
            for (int t = 0; t < TSRC; t++) {
                float4 h4 = sh_h4[t * 8 + i4];
                acc[t] = fmaf(h4.x, w0, fmaf(h4.y, w1, fmaf(h4.z, w2, fmaf(h4.w, w3, acc[t]))));
            }
        }
#pragma unroll
        for (int t = 0; t < TSRC; t++) sh_G[t * (GP * D) + p * D + o] = acc[t];
    }
    __syncthreads();

    // ---- phase 2: edge streaming from this block's bin ----
    int bs = bin * cap;
    int nE = min(bincnt[bin], cap);
    int grp = tid >> 3;        // 68 groups of 8
    int j8 = tid & 7;
    int iters = (nE + 67) / 68;
    for (int it = 0; it < iters; it++) {
        int j = it * 68 + grp;
        bool valid = j < nE;
        int eid = bins[bs + (valid ? j : 0)];
        int s = srcA[eid];
        int t = s - first;
        int d = dstA[eid];
        float inv = 1.0f / (float)max(cntD[d], 1);
        float2 c2 = ((const float2*)(ef + (size_t)eid * DPF))[j8];
        const float* Gt = sh_G + t * (GP * D);
        float4 a = {0.f, 0.f, 0.f, 0.f};
#pragma unroll
        for (int p = 0; p < GP; p++) {
            float cp;
            if (p < DPF) cp = __shfl_sync(0xffffffffu, (p & 1) ? c2.y : c2.x, p >> 1, 8);
            else cp = 1.f;
            float4 g4 = ((const float4*)(Gt + p * D))[j8];
            a.x = fmaf(cp, g4.x, a.x);
            a.y = fmaf(cp, g4.y, a.y);
            a.z = fmaf(cp, g4.z, a.z);
            a.w = fmaf(cp, g4.w, a.w);
        }
        a.x *= inv; a.y *= inv; a.z *= inv; a.w *= inv;
        if (valid) red_add_f4(out_cell + (size_t)d * D + j8 * 4, a);
    }
}

// net + gcell epilogue (cell outputs are produced by k_nn directly)
#define NBF_NET  (N_NET / 8)            // 1250
#define NBF_GC   (N_GCELL / 8)          // 2500
__global__ void k_final_netgc(const float* __restrict__ net_feat,
                              const float* __restrict__ W_pins, const float* __restrict__ b_pins,
                              const float* __restrict__ W_net, const float* __restrict__ b_net,
                              const float* __restrict__ W_connect, const float* __restrict__ b_connect,
                              const float* __restrict__ W_pt, const float* __restrict__ b_pt,
                              float* __restrict__ out_net, float* __restrict__ out_gcell) {
    __shared__ float sW1[D * D], sW2[D * D];
    int b = blockIdx.x;
    if (b < NBF_NET) {
        for (int i = threadIdx.x; i < D * D; i += 256) { sW1[i] = W_pins[i]; sW2[i] = W_net[i]; }
        __syncthreads();
        int n = b * 8 + (threadIdx.x >> 5);
        int o = threadIdx.x & 31;
        float acc = 0.f, acc2 = 0.f;
#pragma unroll
        for (int i = 0; i < D; i++) {
            acc  = fmaf(g_agg_net[n * D + i], sW1[i * D + o], acc);
            acc2 = fmaf(net_feat[n * D + i],  sW2[i * D + o], acc2);
        }
        float ddn = rsqrtf((float)max(g_cnt_pins_dst[n], 1));
        out_net[n * D + o] = acc * ddn + b_pins[o] + acc2 + b_net[o];
        return;
    }
    {
        for (int i = threadIdx.x; i < D * D; i += 256) { sW1[i] = W_connect[i]; sW2[i] = W_pt[i]; }
        __syncthreads();
        int g = (b - NBF_NET) * 8 + (threadIdx.x >> 5);
        int o = threadIdx.x & 31;
        float acc = 0.f, acc2 = 0.f;
#pragma unroll
        for (int i = 0; i < D; i++) {
            acc  = fmaf(g_agg_gc_c[g * D + i],  sW1[i * D + o], acc);
            acc2 = fmaf(g_agg_gc_pt[g * D + i], sW2[i * D + o], acc2);
        }
        float dc = rsqrtf((float)max(g_cnt_connect_dst[g], 1));
        float dp = rsqrtf((float)max(g_cnt_pt_dst[g], 1));
        out_gcell[g * D + o] = acc * dc + b_connect[o] + acc2 * dp + b_pt[o];
    }
}

// ---------------- launch ----------------

extern "C" void kernel_launch(void* const* d_in, const int* in_sizes, int n_in,
                              void* d_out, int out_size) {
    const float* node_feat   = (const float*)d_in[0];
    const float* net_feat    = (const float*)d_in[1];
    const float* pin_feat    = (const float*)d_in[2];
    const float* hanna_feat  = (const float*)d_in[3];
    const float* edge_feat   = (const float*)d_in[4];
    const int* pins_src      = (const int*)d_in[5];
    const int* pins_dst      = (const int*)d_in[6];
    const int* pinned_src    = (const int*)d_in[7];
    const int* pinned_dst    = (const int*)d_in[8];
    const int* connect_src   = (const int*)d_in[9];
    const int* connect_dst   = (const int*)d_in[10];
    const int* pt_src        = (const int*)d_in[11];
    const int* pt_dst        = (const int*)d_in[12];
    const int* pf_src        = (const int*)d_in[13];
    const int* pf_dst        = (const int*)d_in[14];
    const float* W_net       = (const float*)d_in[15];
    const float* b_net       = (const float*)d_in[16];
    const float* W_topo      = (const float*)d_in[17];
    const float* b_topo      = (const float*)d_in[18];
    const float* W_pins      = (const float*)d_in[19];
    const float* b_pins      = (const float*)d_in[20];
    const float* W_connect   = (const float*)d_in[21];
    const float* b_connect   = (const float*)d_in[22];
    const float* W_pt        = (const float*)d_in[23];
    const float* b_pt        = (const float*)d_in[24];
    const float* b_pinned    = (const float*)d_in[25];
    const float* b_pf        = (const float*)d_in[26];

    float* out       = (float*)d_out;
    float* out_cell  = out;
    float* out_net   = out + (size_t)N_CELL * D;
    float* out_gcell = out + (size_t)(N_CELL + N_NET) * D;

    static cudaStream_t s1 = nullptr;
    static cudaEvent_t evZ = nullptr, evNN = nullptr;
    if (s1 == nullptr) {
        cudaStreamCreateWithFlags(&s1, cudaStreamNonBlocking);
        cudaEventCreateWithFlags(&evZ, cudaEventDisableTiming);
        cudaEventCreateWithFlags(&evNN, cudaEventDisableTiming);
    }

    // main: zero (also bias-inits out_cell)
    k_zero<<<1024, 256>>>(b_pinned, b_pf, out_cell);
    cudaEventRecord(evZ, 0);

    // s1 branch: prep_nn -> nn (writes out_cell directly)
    cudaStreamWaitEvent(s1, evZ, 0);
    k_prep_nn<<<4 * RBLK, 256, 0, s1>>>(pinned_src, pinned_dst, pf_src, pf_dst);
    k_nn<<<NB_NET_NN + NB_GC_NN, 544, 0, s1>>>(net_feat, hanna_feat, W_topo, b_topo,
                                               pin_feat, edge_feat,
                                               pinned_src, pinned_dst, pf_src, pf_dst,
                                               out_cell);
    cudaEventRecord(evNN, s1);

    // main branch: prep_gc -> gc_scatter -> final_netgc (writes out_net/out_gcell)
    k_prep_gc<<<6 * RBLK, 256>>>(pins_src, pins_dst, connect_src, connect_dst,
                                 pt_src, pt_dst);
    k_gc_scatter<<<(3 * NE * 8 + 255) / 256, 256>>>(node_feat, hanna_feat,
                                                    pins_src, pins_dst,
                                                    connect_src, connect_dst,
                                                    pt_src, pt_dst);
    k_final_netgc<<<NBF_NET + NBF_GC, 256>>>(net_feat, W_pins, b_pins, W_net, b_net,
                                             W_connect, b_connect, W_pt, b_pt,
                                             out_net, out_gcell);

    // join
    cudaStreamWaitEvent(0, evNN, 0);
}